// round 9
// baseline (speedup 1.0000x reference)
#include <cuda_runtime.h>

// Problem shapes (fixed by setup_inputs): B=4, N=2048, C=3
#define BD 4
#define NP 2048          // proposals per image = candidates per (image,class)
#define MAXDET 100
#define CAPC 256         // max selected candidates per class
#define TSELC 160        // per-class selection target (> ~111 needed for 100 kept)
#define HB0 0x400        // first histogram bin (12-bit key bin space)
#define NHB 64           // histogram bins

// Inter-kernel scratch (device globals — no allocation allowed)
__device__ unsigned long long gk_key[2 * BD][128];
__device__ float4             gk_box[2 * BD][128];
__device__ int                gk_cnt[2 * BD];

struct __align__(16) SM {
    float4 box[NP];                   // all candidate boxes for this class (32 KB)
    unsigned long long key[NP];       // all 2048 keys (intact for fallback, 16 KB)
    unsigned long long selkey[CAPC];  // selected (unordered, padded)
    unsigned long long skey[CAPC];    // selected (sorted)
    float4 sbox[CAPC];                // selected boxes (sorted order, zero-padded)
    float  sarea[CAPC];
    unsigned int mask[CAPC][8];       // suppression bitmask (8 KB)
    float4 kbox[MAXDET];              // fallback kept boxes
    float  karea[MAXDET];
    unsigned int hist[NHB];
    unsigned int kbits[8];            // keep bits from resolution
    unsigned int kpre[8];             // excl prefix of keep popcounts
    int c1_rel, n_valid, n_sel, fb, s_cnt, cnt_sel;
};

__device__ __forceinline__ float read_dim(const void* p) {
    if (p == nullptr) return 800.0f;
    int v = *(const int*)p;
    if (v > 0 && v < 1000000) return (float)v;   // stored as int32
    return *(const float*)p;                      // stored as float32
}

__device__ __forceinline__ int hbin_of(unsigned long long k) {
    int b12 = (int)(k >> 52);
    return min(max(b12 - HB0, 0), NHB - 1);
}

// ---------------------------------------------------------------------------
// Kernel 1: one block per (image, class). Full per-class pipeline.
// ---------------------------------------------------------------------------
__global__ __launch_bounds__(1024, 1)
void percls_kernel(const float* __restrict__ logits,
                   const float* __restrict__ reg,
                   const float* __restrict__ props,
                   const void* ph, const void* pw) {
    extern __shared__ unsigned char smem_raw[];
    SM& s = *reinterpret_cast<SM*>(smem_raw);

    const int bx   = blockIdx.x;
    const int b    = bx >> 1;
    const int c    = bx & 1;          // class index 0/1 -> label 1/2
    const int tid  = threadIdx.x;
    const int lane = tid & 31;
    const unsigned FULL = 0xFFFFFFFFu;
    const float H = read_dim(ph), W = read_dim(pw);
    const float SCL = 4.135166556742356f;   // ln(1000/16)

    if (tid == 0) { s.fb = 0; s.cnt_sel = 0; s.n_sel = 0; }
    if (tid < NHB) s.hist[tid] = 0;
    __syncthreads();

    // ---- Phase A: prep (softmax for this class + decode + clip + key + hist) ----
    for (int p = tid; p < NP; p += 1024) {
        const float* L = logits + (b * NP + p) * 3;
        float l0 = L[0], l1 = L[1], l2 = L[2];
        float mx = fmaxf(l0, fmaxf(l1, l2));
        float e0 = __expf(l0 - mx), e1 = __expf(l1 - mx), e2 = __expf(l2 - mx);
        float sc = (c == 0 ? e1 : e2) * __fdividef(1.0f, e0 + e1 + e2);

        const float4 P = *(const float4*)(props + (b * NP + p) * 4);
        float pw_ = P.z - P.x, ph_ = P.w - P.y;
        float cx = P.x + 0.5f * pw_, cy = P.y + 0.5f * ph_;

        const float4 R = *(const float4*)(reg + (b * NP + p) * 12 + 4 + 4 * c);
        float dx = R.x * 0.1f;
        float dy = R.y * 0.1f;
        float dw = fminf(R.z * 0.2f, SCL);
        float dh = fminf(R.w * 0.2f, SCL);
        float pcx = dx * pw_ + cx;
        float pcy = dy * ph_ + cy;
        float nw  = __expf(dw) * pw_;
        float nh  = __expf(dh) * ph_;
        float x1 = fminf(fmaxf(pcx - 0.5f * nw, 0.0f), W);
        float y1 = fminf(fmaxf(pcy - 0.5f * nh, 0.0f), H);
        float x2 = fminf(fmaxf(pcx + 0.5f * nw, 0.0f), W);
        float y2 = fminf(fmaxf(pcy + 0.5f * nh, 0.0f), H);
        bool valid = (sc > 0.05f) && ((x2 - x1) >= 0.01f) && ((y2 - y1) >= 0.01f);
        s.box[p] = make_float4(x1, y1, x2, y2);
        unsigned long long key;
        if (valid) {
            unsigned mono = __float_as_uint(sc) | 0x80000000u;    // sc > 0
            key = (((unsigned long long)(~mono)) << 32) | (unsigned)p;
            atomicAdd(&s.hist[hbin_of(key)], 1u);
        } else {
            key = 0xFFFFFFFF00000000ull | (unsigned)p;            // bin 0xFFF
        }
        s.key[p] = key;
    }
    __syncthreads();

    // ---- Phase B: single-warp cutoff scan over 64 bins ----
    if (tid < 32) {   // 2 bins per lane
        unsigned v0 = s.hist[2 * lane], v1 = s.hist[2 * lane + 1];
        unsigned lsum = v0 + v1;
        unsigned inc = lsum;
        #pragma unroll
        for (int o = 1; o < 32; o <<= 1) {
            unsigned x = __shfl_up_sync(FULL, inc, o);
            if (lane >= o) inc += x;
        }
        unsigned excl = inc - lsum;
        unsigned total = __shfl_sync(FULL, inc, 31);
        bool cross = ((int)excl < TSELC) && ((int)(excl + lsum) >= TSELC);
        unsigned mb = __ballot_sync(FULL, cross);
        if (lane == 0) s.n_valid = (int)total;
        if (mb == 0) {
            if (lane == 0) { s.c1_rel = NHB - 1; s.n_sel = min((int)total, CAPC);
                             if ((int)total > CAPC) s.fb = 1; }
        } else {
            int src = __ffs(mb) - 1;
            if (lane == src) {
                int rel, incl;
                if ((int)excl + (int)v0 >= TSELC) { rel = 2 * src;     incl = (int)excl + (int)v0; }
                else                              { rel = 2 * src + 1; incl = (int)excl + (int)lsum; }
                if (incl > CAPC) s.fb = 1;
                else             { s.c1_rel = rel; s.n_sel = incl; }
            }
        }
    }
    __syncthreads();

    const int n_sel = s.n_sel;
    const int c1r   = s.c1_rel;

    if (!s.fb) {
        // ---- compact selected keys (unordered) ----
        for (int m = tid; m < NP; m += 1024) {
            unsigned long long k = s.key[m];
            if ((int)(k >> 52) != 0xFFF && hbin_of(k) <= c1r) {
                int pos = atomicAdd(&s.cnt_sel, 1);
                if (pos < CAPC) s.selkey[pos] = k;
            }
        }
    }
    __syncthreads();
    for (int t = tid; t < CAPC; t += 1024)
        if (t >= n_sel) s.selkey[t] = 0xFFFFFFFFFFFFF000ull + (unsigned)t;
    __syncthreads();

    // ---- Phase C: rank sort, 2 threads per element ----
    const int n_pad = (n_sel + 31) & ~31;
    if (tid < 2 * n_pad) {
        int e = tid >> 1, half = tid & 1;
        unsigned long long k = s.selkey[e];
        int j0 = half ? (n_pad >> 1) : 0;
        int j1 = half ? n_pad : (n_pad >> 1);
        int r = 0;
        #pragma unroll 8
        for (int j = j0; j < j1; j++) r += (s.selkey[j] < k);
        r += __shfl_xor_sync(FULL, r, 1);
        if (!half) s.skey[r] = k;
    }
    __syncthreads();

    // ---- Phase D: gather boxes/areas (zero-padded to CAPC) ----
    if (tid < CAPC) {
        if (tid < n_sel) {
            int idx = (int)(unsigned)s.skey[tid];
            float4 bb = s.box[idx];
            s.sbox[tid]  = bb;
            s.sarea[tid] = (bb.z - bb.x) * (bb.w - bb.y);
        } else {
            s.sbox[tid] = make_float4(0.f, 0.f, 0.f, 0.f);
            s.sarea[tid] = 0.f;
        }
    }
    __syncthreads();

    // ---- Phase E: suppression bitmask (zero-padded rows are harmless) ----
    for (int u = tid; u < CAPC * 8; u += 1024) {
        int i = u >> 3, w = u & 7;
        unsigned bits = 0;
        if (i < n_sel && w >= (i >> 5) && (w << 5) < n_sel) {
            float4 bi = s.sbox[i];
            float  ai = s.sarea[i];
            int j0 = w << 5;
            #pragma unroll
            for (int l = 0; l < 32; l++) {
                int j = j0 + l;
                float4 bj = s.sbox[j];
                float iw = fminf(bi.z, bj.z) - fmaxf(bi.x, bj.x);
                float ih = fminf(bi.w, bj.w) - fmaxf(bi.y, bj.y);
                iw = fmaxf(iw, 0.0f); ih = fmaxf(ih, 0.0f);
                float inter = iw * ih;
                bool sp = (j > i) && (2.0f * inter > ai + s.sarea[j] - inter + 1e-7f);
                bits |= (sp ? (1u << l) : 0u);
            }
        }
        s.mask[i][w] = bits;
    }
    __syncthreads();

    // ---- Phase F: greedy resolution (warp 0) ----
    if (tid < 32) {
        unsigned removed = 0, kb = 0;
        int cnt = 0;
        for (int i = 0; i < n_sel; i++) {
            unsigned rw = __shfl_sync(FULL, removed, i >> 5);
            if (!((rw >> (i & 31)) & 1u)) {
                if (lane == (i >> 5)) kb |= 1u << (i & 31);
                cnt++;
                if (lane < 8) removed |= s.mask[i][lane];
                if (cnt == MAXDET) break;
            }
        }
        if (lane < 8) s.kbits[lane] = kb;
        if (lane == 0) {
            s.s_cnt = cnt;
            if (cnt < MAXDET && s.n_valid > n_sel) s.fb = 1;   // prefix exhausted
        }
    }
    __syncthreads();

    if (!s.fb) {
        // ---- Phase G: scatter kept list to global scratch ----
        if (tid < 8) {   // tiny serial prefix of 8 popcounts (lane-parallel is overkill)
            int acc = 0;
            for (int w2 = 0; w2 < tid; w2++) acc += __popc(s.kbits[w2]);
            s.kpre[tid] = (unsigned)acc;
        }
        __syncthreads();
        if (tid < CAPC && tid < n_sel) {
            unsigned kb = s.kbits[tid >> 5];
            if ((kb >> (tid & 31)) & 1u) {
                unsigned low = (1u << (tid & 31)) - 1u;
                int pos = (int)s.kpre[tid >> 5] + __popc(kb & low);
                gk_key[bx][pos] = s.skey[tid];
                gk_box[bx][pos] = s.sbox[tid];
            }
        }
        if (tid == 0) gk_cnt[bx] = s.s_cnt;
        return;
    }

    // ================= FALLBACK: bitonic sort (2048) + warp NMS =================
    #pragma unroll 1
    for (int k = 2; k <= NP; k <<= 1) {
        #pragma unroll 1
        for (int j = k >> 1; j > 0; j >>= 1) {
            int p = tid;                                     // 1024 pairs exactly
            int i = ((p & ~(j - 1)) << 1) | (p & (j - 1));
            int l = i | j;
            bool up = ((i & k) == 0);
            unsigned long long a = s.key[i], cc = s.key[l];
            if ((a > cc) == up) { s.key[i] = cc; s.key[l] = a; }
            __syncthreads();
        }
    }

    if (tid < 32) {
        int cnt = 0;
        for (int t = 0; t < NP; t++) {
            unsigned long long key = s.key[t];
            unsigned hi = (unsigned)(key >> 32);
            if (hi == 0xFFFFFFFFu) break;
            int idx = (int)(unsigned)key;
            float4 bc = s.box[idx];                          // LDS — boxes live in smem
            float area = (bc.z - bc.x) * (bc.w - bc.y);
            bool sup = false;
            for (int j = lane; j < cnt; j += 32) {
                float4 kb = s.kbox[j];
                float iw = fminf(bc.z, kb.z) - fmaxf(bc.x, kb.x);
                float ih = fminf(bc.w, kb.w) - fmaxf(bc.y, kb.y);
                iw = fmaxf(iw, 0.0f); ih = fmaxf(ih, 0.0f);
                float inter = iw * ih;
                if (2.0f * inter > area + s.karea[j] - inter + 1e-7f) sup = true;
            }
            if (__ballot_sync(FULL, sup) == 0u) {
                if (lane == 0) {
                    s.kbox[cnt] = bc; s.karea[cnt] = area;
                    gk_key[bx][cnt] = key;
                    gk_box[bx][cnt] = bc;
                }
                cnt++;
                __syncwarp();
                if (cnt == MAXDET) break;
            }
        }
        if (lane == 0) gk_cnt[bx] = cnt;
    }
}

// ---------------------------------------------------------------------------
// Kernel 2: per-image rank-merge of the two per-class kept lists -> top-100.
// Output layout (float32): boxes [B,100,4] | scores [B,100] | labels [B,100] | keep [B,100]
// ---------------------------------------------------------------------------
__global__ void merge_kernel(float* __restrict__ out) {
    const int b   = blockIdx.x;
    const int tid = threadIdx.x;

    float* oB = out;
    float* oS = out + BD * MAXDET * 4;
    float* oL = oS + BD * MAXDET;
    float* oK = oL + BD * MAXDET;

    // zero-fill
    if (tid < MAXDET) {
        int base = (b * MAXDET + tid) * 4;
        oB[base + 0] = 0.f; oB[base + 1] = 0.f; oB[base + 2] = 0.f; oB[base + 3] = 0.f;
        oS[b * MAXDET + tid] = 0.f;
        oL[b * MAXDET + tid] = 0.f;
        oK[b * MAXDET + tid] = 0.f;
    }
    __syncthreads();

    const int nA = gk_cnt[2 * b], nB = gk_cnt[2 * b + 1];
    const int tot = nA + nB;
    if (tid < tot) {
        int list = (tid < nA) ? 0 : 1;
        int i    = list ? (tid - nA) : tid;
        int gi   = 2 * b + list;
        int go   = 2 * b + (1 - list);
        int n_o  = list ? nA : nB;
        unsigned long long key = gk_key[gi][i];
        int r = i;
        for (int j = 0; j < n_o; j++) r += (gk_key[go][j] < key);   // keys globally unique
        if (r < MAXDET) {
            float4 bb = gk_box[gi][i];
            float sc = __uint_as_float((~(unsigned)(key >> 32)) & 0x7FFFFFFFu);
            int base = (b * MAXDET + r) * 4;
            oB[base + 0] = bb.x; oB[base + 1] = bb.y;
            oB[base + 2] = bb.z; oB[base + 3] = bb.w;
            oS[b * MAXDET + r] = sc;
            oL[b * MAXDET + r] = (float)(list + 1);
            oK[b * MAXDET + r] = 1.0f;
        }
    }
}

// ---------------------------------------------------------------------------
extern "C" void kernel_launch(void* const* d_in, const int* in_sizes, int n_in,
                              void* d_out, int out_size) {
    const float* logits = nullptr;
    const float* reg    = nullptr;
    const float* props  = nullptr;
    const void*  dims[2] = {nullptr, nullptr};
    int nd = 0;
    for (int i = 0; i < n_in; i++) {
        int sz = in_sizes[i];
        if      (sz == BD * NP * 3)  logits = (const float*)d_in[i];
        else if (sz == BD * NP * 12) reg    = (const float*)d_in[i];
        else if (sz == BD * NP * 4)  props  = (const float*)d_in[i];
        else if (sz == 1 && nd < 2)  dims[nd++] = d_in[i];
    }

    const int smem_bytes = (int)sizeof(SM);
    cudaFuncSetAttribute(percls_kernel, cudaFuncAttributeMaxDynamicSharedMemorySize, smem_bytes);
    percls_kernel<<<2 * BD, 1024, smem_bytes>>>(logits, reg, props, dims[0], dims[1]);
    merge_kernel<<<BD, 256>>>((float*)d_out);
}

// round 10
// speedup vs baseline: 1.0145x; 1.0145x over previous
#include <cuda_runtime.h>

// Problem shapes (fixed by setup_inputs): B=4, N=2048, C=3
#define BD 4
#define NP 2048
#define MM 4096          // N * (C-1) candidates per image
#define MAXDET 100
#define CAP 512          // max selected candidates (global prefix)
#define PCCAP 256        // max per-class selected candidates
#define TSEL 160         // selection target (> ~110 consumed by NMS)
#define PRE 512          // fallback: sorted boxes pre-gathered
#define HB0 0x400        // first histogram bin (12-bit key bin space)
#define NHB 64           // histogram bins

struct __align__(16) SM {
    float4 box[MM];                   // all candidate boxes (smem-resident)
    unsigned long long key[MM];       // all 4096 keys (intact for fallback)
    unsigned long long selkey[CAP];   // selected (unordered, padded)
    unsigned long long skey[CAP];     // selected (sorted)
    float4 sbox[CAP];                 // boxes in global sorted order
    float4 cbox[2][PCCAP];            // per-class boxes (score order, zero-padded)
    float4 kbox[MAXDET];              // fallback kept boxes
    unsigned int hist[NHB];
    unsigned int mask[2][PCCAP][8];   // per-class suppression bitmask
    float carea[2][PCCAP];
    unsigned int labw[16];            // label-1 bit per global rank
    unsigned int pre1[16];            // excl prefix of label-1 popcounts
    unsigned int kbits[2][8];         // per-class keep bits
    unsigned int kw[16];              // global keep bits
    unsigned int kpre[16];            // excl prefix of keep popcounts
    unsigned short clsrank[CAP];
    float karea[MAXDET]; float kscore[MAXDET]; int klab[MAXDET];
    int cn[2];
    int c1_rel, n_valid, n_sel, fb, s_cnt, cnt_sel, kept_total;
};

__device__ __forceinline__ float read_dim(const void* p) {
    if (p == nullptr) return 800.0f;
    int v = *(const int*)p;
    if (v > 0 && v < 1000000) return (float)v;   // stored as int32
    return *(const float*)p;                      // stored as float32
}

__device__ __forceinline__ int hbin_of(unsigned long long k) {
    int b12 = (int)(k >> 52);
    return min(max(b12 - HB0, 0), NHB - 1);
}

__global__ __launch_bounds__(1024, 1)
void fused_kernel(const float* __restrict__ logits,
                  const float* __restrict__ reg,
                  const float* __restrict__ props,
                  const void* ph, const void* pw,
                  float* __restrict__ out) {
    extern __shared__ unsigned char smem_raw[];
    SM& s = *reinterpret_cast<SM*>(smem_raw);

    const int b    = blockIdx.x;
    const int tid  = threadIdx.x;
    const int lane = tid & 31;
    const int wid  = tid >> 5;
    const unsigned FULL = 0xFFFFFFFFu;
    const float H = read_dim(ph), W = read_dim(pw);
    const float SCL = 4.135166556742356f;   // ln(1000/16)

    float* oB = out;                              // [B,100,4]
    float* oS = out + BD * MAXDET * 4;            // [B,100]
    float* oL = oS + BD * MAXDET;                 // [B,100]
    float* oK = oL + BD * MAXDET;                 // [B,100]

    // ---- early output zero-fill (fire-and-forget; ordered before the tail
    //      scatter by the many intervening barriers; fallback overwrites all) ----
    for (int j = tid; j < MAXDET; j += 1024) {
        int base = (b * MAXDET + j) * 4;
        oB[base + 0] = 0.f; oB[base + 1] = 0.f; oB[base + 2] = 0.f; oB[base + 3] = 0.f;
        oS[b * MAXDET + j] = 0.f;
        oL[b * MAXDET + j] = 0.f;
        oK[b * MAXDET + j] = 0.f;
    }

    if (tid == 0) { s.fb = 0; s.cnt_sel = 0; s.n_sel = 0; }
    if (tid < NHB) s.hist[tid] = 0;
    __syncthreads();   // hist must be zero before Phase A's fused atomics

    // ---- Phase A: prep (softmax + decode + clip + key + aggregated histogram) ----
    for (int p = tid; p < NP; p += 1024) {
        const float* L = logits + (b * NP + p) * 3;
        float l0 = L[0], l1 = L[1], l2 = L[2];
        float mx = fmaxf(l0, fmaxf(l1, l2));
        float e0 = __expf(l0 - mx), e1 = __expf(l1 - mx), e2 = __expf(l2 - mx);
        float inv = __fdividef(1.0f, e0 + e1 + e2);
        float sc1 = e1 * inv, sc2 = e2 * inv;

        const float4 P = *(const float4*)(props + (b * NP + p) * 4);
        float pw_ = P.z - P.x, ph_ = P.w - P.y;
        float cx = P.x + 0.5f * pw_, cy = P.y + 0.5f * ph_;

        const float4 R1 = *(const float4*)(reg + (b * NP + p) * 12 + 4);
        const float4 R2 = *(const float4*)(reg + (b * NP + p) * 12 + 8);

        #pragma unroll
        for (int cc = 0; cc < 2; cc++) {
            float4 R = cc ? R2 : R1;
            float sc = cc ? sc2 : sc1;
            int   m  = 2 * p + cc;
            float dx = R.x * 0.1f;
            float dy = R.y * 0.1f;
            float dw = fminf(R.z * 0.2f, SCL);
            float dh = fminf(R.w * 0.2f, SCL);
            float pcx = dx * pw_ + cx;
            float pcy = dy * ph_ + cy;
            float nw  = __expf(dw) * pw_;
            float nh  = __expf(dh) * ph_;
            float x1 = fminf(fmaxf(pcx - 0.5f * nw, 0.0f), W);
            float y1 = fminf(fmaxf(pcy - 0.5f * nh, 0.0f), H);
            float x2 = fminf(fmaxf(pcx + 0.5f * nw, 0.0f), W);
            float y2 = fminf(fmaxf(pcy + 0.5f * nh, 0.0f), H);
            bool valid = (sc > 0.05f) && ((x2 - x1) >= 0.01f) && ((y2 - y1) >= 0.01f);
            s.box[m] = make_float4(x1, y1, x2, y2);
            unsigned long long key;
            int bin;
            if (valid) {
                unsigned mono = __float_as_uint(sc) | 0x80000000u;    // sc > 0
                key = (((unsigned long long)(~mono)) << 32) | (unsigned)m;
                bin = hbin_of(key);
            } else {
                key = 0xFFFFFFFF00000000ull | (unsigned)m;            // bin 0xFFF
                bin = NHB;                                            // sentinel
            }
            s.key[m] = key;
            // warp-aggregated histogram add (full-warp convergent here)
            unsigned mg = __match_any_sync(FULL, bin);
            int leader = __ffs(mg) - 1;
            if (lane == leader && bin < NHB)
                atomicAdd(&s.hist[bin], (unsigned)__popc(mg));
        }
    }
    __syncthreads();

    // ---- Phase B: single-warp cutoff scan over 64 bins ----
    if (tid < 32) {   // 2 bins per lane, ordered scan
        unsigned v0 = s.hist[2 * lane], v1 = s.hist[2 * lane + 1];
        unsigned lsum = v0 + v1;
        unsigned inc = lsum;
        #pragma unroll
        for (int o = 1; o < 32; o <<= 1) {
            unsigned x = __shfl_up_sync(FULL, inc, o);
            if (lane >= o) inc += x;
        }
        unsigned excl = inc - lsum;
        unsigned total = __shfl_sync(FULL, inc, 31);
        bool cross = ((int)excl < TSEL) && ((int)(excl + lsum) >= TSEL);
        unsigned mb = __ballot_sync(FULL, cross);
        if (lane == 0) s.n_valid = (int)total;
        if (mb == 0) {
            if (lane == 0) { s.c1_rel = NHB - 1; s.n_sel = (int)total; }  // take all valid
        } else {
            int src = __ffs(mb) - 1;
            if (lane == src) {
                int rel, incl;
                if ((int)excl + (int)v0 >= TSEL) { rel = 2 * src;     incl = (int)excl + (int)v0; }
                else                             { rel = 2 * src + 1; incl = (int)excl + (int)lsum; }
                if (incl > CAP) s.fb = 1;                      // fat cutoff bin -> fallback
                else            { s.c1_rel = rel; s.n_sel = incl; }
            }
        }
    }
    __syncthreads();

    const int n_sel = s.n_sel;
    const int c1r   = s.c1_rel;

    // ---- compact selected keys (warp-aggregated) ----
    if (!s.fb) {
        for (int m = tid; m < MM; m += 1024) {
            unsigned long long k = s.key[m];
            bool sel = ((int)(k >> 52) != 0xFFF) && (hbin_of(k) <= c1r);
            unsigned bal = __ballot_sync(FULL, sel);
            if (bal) {
                int leader = __ffs(bal) - 1;
                int base = 0;
                if (lane == leader) base = atomicAdd(&s.cnt_sel, __popc(bal));
                base = __shfl_sync(FULL, base, leader);
                if (sel) {
                    int pos = base + __popc(bal & ((1u << lane) - 1u));
                    if (pos < CAP) s.selkey[pos] = k;
                }
            }
        }
    }
    __syncthreads();
    for (int t = tid; t < CAP; t += 1024)
        if (t >= n_sel) s.selkey[t] = 0xFFFFFFFFFFFFF000ull + (unsigned)t;
    __syncthreads();

    // ---- Phase C: rank sort, 4 threads per element (quads lane-aligned) ----
    const int n_pad = (n_sel + 31) & ~31;
    if (n_pad <= 256) {
        if (tid < 4 * n_pad) {
            int e = tid >> 2, q = tid & 3;
            unsigned long long k = s.selkey[e];
            int qn = n_pad >> 2;
            int j0 = q * qn, j1 = j0 + qn;
            int r = 0;
            #pragma unroll 8
            for (int j = j0; j < j1; j++) r += (s.selkey[j] < k);
            r += __shfl_xor_sync(FULL, r, 1);
            r += __shfl_xor_sync(FULL, r, 2);
            if (q == 0) s.skey[r] = k;
        }
    } else {
        if (tid < 2 * n_pad) {
            int e = tid >> 1, half = tid & 1;
            unsigned long long k = s.selkey[e];
            int j0 = half ? (n_pad >> 1) : 0;
            int j1 = half ? n_pad : (n_pad >> 1);
            int r = 0;
            #pragma unroll 8
            for (int j = j0; j < j1; j++) r += (s.selkey[j] < k);
            r += __shfl_xor_sync(FULL, r, 1);
            if (!half) s.skey[r] = k;
        }
    }
    __syncthreads();

    // ---- Phase D: gather + per-class partition ----
    bool act = false; int lab = 0; float4 bb = make_float4(0.f, 0.f, 0.f, 0.f);
    if (tid < 512) {
        act = (tid < n_sel);
        if (act) {
            int idx = (int)(unsigned)s.skey[tid];
            lab = idx & 1;
            bb = s.box[idx];
            s.sbox[tid] = bb;
        }
        unsigned bal = __ballot_sync(FULL, act && lab);
        if (lane == 0) s.labw[wid] = bal;
    }
    __syncthreads();
    if (tid < 32) {
        unsigned c = (lane < 16) ? __popc(s.labw[lane]) : 0;
        unsigned inc = c;
        #pragma unroll
        for (int o = 1; o < 32; o <<= 1) {
            unsigned x = __shfl_up_sync(FULL, inc, o);
            if (lane >= o) inc += x;
        }
        if (lane < 16) s.pre1[lane] = inc - c;
        unsigned cn1 = __shfl_sync(FULL, inc, 15);
        if (lane == 0) {
            s.cn[1] = (int)cn1;
            s.cn[0] = n_sel - (int)cn1;
            if (s.cn[0] > PCCAP || s.cn[1] > PCCAP) s.fb = 1;
        }
    }
    __syncthreads();
    if (tid < 512 && act) {
        unsigned low = (1u << lane) - 1u;
        int c1below = (int)s.pre1[wid] + __popc(s.labw[wid] & low);
        int r = lab ? c1below : (tid - c1below);
        s.clsrank[tid] = (unsigned short)r;
        if (r < PCCAP) {
            s.cbox[lab][r]  = bb;
            s.carea[lab][r] = (bb.z - bb.x) * (bb.w - bb.y);
        }
    }
    // zero-pad per-class tails (disjoint addresses from scatter above)
    for (int u = tid; u < 2 * PCCAP; u += 1024) {
        int c = u >> 8, r = u & (PCCAP - 1);
        if (r >= min(s.cn[c], PCCAP)) {
            s.cbox[c][r] = make_float4(0.f, 0.f, 0.f, 0.f);
            s.carea[c][r] = 0.f;
        }
    }
    __syncthreads();

    // ---- Phase E: per-class suppression bitmask ----
    for (int u = tid; u < 2 * PCCAP * 8; u += 1024) {
        int c = u >> 11, i = (u >> 3) & (PCCAP - 1), w = u & 7;
        unsigned bits = 0;
        int nc_ = s.cn[c];
        if (i < nc_ && w >= (i >> 5) && (w << 5) < nc_) {
            float4 bi = s.cbox[c][i];
            float  ai = s.carea[c][i];
            int j0 = w << 5;
            #pragma unroll
            for (int l = 0; l < 32; l++) {
                int j = j0 + l;
                float4 bj = s.cbox[c][j];
                float iw = fminf(bi.z, bj.z) - fmaxf(bi.x, bj.x);
                float ih = fminf(bi.w, bj.w) - fmaxf(bi.y, bj.y);
                iw = fmaxf(iw, 0.0f); ih = fmaxf(ih, 0.0f);
                float inter = iw * ih;
                bool sp = (j > i) && (2.0f * inter > ai + s.carea[c][j] - inter + 1e-7f);
                bits |= (sp ? (1u << l) : 0u);
            }
        }
        s.mask[c][i][w] = bits;
    }
    __syncthreads();

    // ---- Phase F: per-class greedy resolution (warps 0 and 1 in parallel) ----
    if (wid < 2) {
        int c = wid;
        int nc_ = min(s.cn[c], PCCAP);
        unsigned removed = 0, kb = 0;
        int cnt = 0;
        for (int i = 0; i < nc_; i++) {
            unsigned rw = __shfl_sync(FULL, removed, i >> 5);
            if (!((rw >> (i & 31)) & 1u)) {
                if (lane == (i >> 5)) kb |= 1u << (i & 31);
                cnt++;
                if (lane < 8) removed |= s.mask[c][i][lane];
                if (cnt == MAXDET) break;
            }
        }
        if (lane < 8) s.kbits[c][lane] = kb;
    }
    __syncthreads();

    // ---- Phase G: merge kept flags back to global order ----
    bool kflag = false;
    if (tid < 512) {
        if (act) {
            int r = s.clsrank[tid];
            kflag = (s.kbits[lab][r >> 5] >> (r & 31)) & 1u;
        }
        unsigned bal = __ballot_sync(FULL, kflag);
        if (lane == 0) s.kw[wid] = bal;
    }
    __syncthreads();
    if (tid < 32) {
        unsigned c = (lane < 16) ? __popc(s.kw[lane]) : 0;
        unsigned inc = c;
        #pragma unroll
        for (int o = 1; o < 32; o <<= 1) {
            unsigned x = __shfl_up_sync(FULL, inc, o);
            if (lane >= o) inc += x;
        }
        if (lane < 16) s.kpre[lane] = inc - c;
        unsigned tot = __shfl_sync(FULL, inc, 15);
        if (lane == 0) {
            s.kept_total = (int)tot;
            if ((int)tot < MAXDET && s.n_valid > n_sel) s.fb = 1;  // prefix exhausted
        }
    }
    __syncthreads();

    if (!s.fb) {
        // scatter kept rows over the early zero-fill
        if (tid < 512 && kflag) {
            unsigned low = (1u << lane) - 1u;
            int pos = (int)s.kpre[wid] + __popc(s.kw[wid] & low);
            if (pos < MAXDET) {
                unsigned long long key = s.skey[tid];
                float sc = __uint_as_float((~(unsigned)(key >> 32)) & 0x7FFFFFFFu);
                float4 bx = s.sbox[tid];
                int base = (b * MAXDET + pos) * 4;
                oB[base + 0] = bx.x; oB[base + 1] = bx.y;
                oB[base + 2] = bx.z; oB[base + 3] = bx.w;
                oS[b * MAXDET + pos] = sc;
                oL[b * MAXDET + pos] = (float)(lab + 1);
                oK[b * MAXDET + pos] = 1.0f;
            }
        }
        return;
    }

    // ================= FALLBACK: full bitonic sort + warp NMS =================
    #pragma unroll 1
    for (int k = 2; k <= MM; k <<= 1) {
        #pragma unroll 1
        for (int j = k >> 1; j > 0; j >>= 1) {
            #pragma unroll
            for (int q = 0; q < 2; q++) {
                int p = tid + q * 1024;
                int i = ((p & ~(j - 1)) << 1) | (p & (j - 1));
                int l = i | j;
                bool up = ((i & k) == 0);
                unsigned long long a = s.key[i], c = s.key[l];
                if ((a > c) == up) { s.key[i] = c; s.key[l] = a; }
            }
            __syncthreads();
        }
    }
    for (int t = tid; t < PRE; t += 1024) {
        int idx = (int)(unsigned)s.key[t];
        s.sbox[t] = s.box[idx];
    }
    __syncthreads();

    if (tid < 32) {
        int cnt = 0;
        for (int t = 0; t < MM; t++) {
            unsigned long long key = s.key[t];
            unsigned hi = (unsigned)(key >> 32);
            if (hi == 0xFFFFFFFFu) break;
            int idx = (int)(unsigned)key;
            int lb = idx & 1;
            float sc = __uint_as_float((~hi) & 0x7FFFFFFFu);
            float4 bc = (t < PRE) ? s.sbox[t] : s.box[idx];
            float area = (bc.z - bc.x) * (bc.w - bc.y);
            bool sup = false;
            for (int j = lane; j < cnt; j += 32) {
                if (s.klab[j] == lb) {
                    float4 kb = s.kbox[j];
                    float iw = fminf(bc.z, kb.z) - fmaxf(bc.x, kb.x);
                    float ih = fminf(bc.w, kb.w) - fmaxf(bc.y, kb.y);
                    iw = fmaxf(iw, 0.0f); ih = fmaxf(ih, 0.0f);
                    float inter = iw * ih;
                    if (2.0f * inter > area + s.karea[j] - inter + 1e-7f) sup = true;
                }
            }
            if (__ballot_sync(FULL, sup) == 0u) {
                if (lane == 0) {
                    s.kbox[cnt] = bc; s.karea[cnt] = area;
                    s.kscore[cnt] = sc; s.klab[cnt] = lb;
                }
                cnt++;
                __syncwarp();
                if (cnt == MAXDET) break;
            }
        }
        if (lane == 0) s.s_cnt = cnt;
    }
    __syncthreads();

    int cnt = s.s_cnt;
    for (int j = tid; j < MAXDET; j += 1024) {
        bool k = (j < cnt);
        float4 bc = k ? s.kbox[j] : make_float4(0.f, 0.f, 0.f, 0.f);
        int base = (b * MAXDET + j) * 4;
        oB[base + 0] = bc.x; oB[base + 1] = bc.y;
        oB[base + 2] = bc.z; oB[base + 3] = bc.w;
        oS[b * MAXDET + j] = k ? s.kscore[j] : 0.0f;
        oL[b * MAXDET + j] = k ? (float)(s.klab[j] + 1) : 0.0f;
        oK[b * MAXDET + j] = k ? 1.0f : 0.0f;
    }
}

// ---------------------------------------------------------------------------
extern "C" void kernel_launch(void* const* d_in, const int* in_sizes, int n_in,
                              void* d_out, int out_size) {
    const float* logits = nullptr;
    const float* reg    = nullptr;
    const float* props  = nullptr;
    const void*  dims[2] = {nullptr, nullptr};
    int nd = 0;
    for (int i = 0; i < n_in; i++) {
        int sz = in_sizes[i];
        if      (sz == BD * NP * 3)  logits = (const float*)d_in[i];
        else if (sz == BD * NP * 12) reg    = (const float*)d_in[i];
        else if (sz == BD * NP * 4)  props  = (const float*)d_in[i];
        else if (sz == 1 && nd < 2)  dims[nd++] = d_in[i];
    }

    const int smem_bytes = (int)sizeof(SM);
    cudaFuncSetAttribute(fused_kernel, cudaFuncAttributeMaxDynamicSharedMemorySize, smem_bytes);
    fused_kernel<<<BD, 1024, smem_bytes>>>(logits, reg, props, dims[0], dims[1], (float*)d_out);
}

// round 11
// speedup vs baseline: 1.0323x; 1.0175x over previous
#include <cuda_runtime.h>

// Problem shapes (fixed by setup_inputs): B=4, N=2048, C=3
#define BD 4
#define NP 2048
#define MM 4096          // N * (C-1) candidates per image
#define MAXDET 100
#define CAP 512          // max selected candidates (global prefix)
#define PCCAP 256        // max per-class selected candidates
#define TSEL 160         // selection target (> ~110 consumed by NMS)
#define PRE 512          // fallback: sorted boxes pre-gathered
#define HB0 0x400        // first histogram bin (12-bit key bin space)
#define NHB 64           // histogram bins

struct __align__(16) SM {
    float4 box[MM];                   // all candidate boxes (smem-resident)
    unsigned long long key[MM];       // all 4096 keys (intact for fallback)
    unsigned long long selkey[CAP];   // selected (unordered, padded)
    unsigned long long skey[CAP];     // selected (sorted)
    float4 sbox[CAP];                 // boxes in global sorted order
    float4 cbox[2][PCCAP];            // per-class boxes (score order, zero-padded)
    float4 kbox[MAXDET];              // fallback kept boxes
    unsigned int hist[NHB];
    unsigned int mask[2][PCCAP][8];   // per-class suppression bitmask
    float carea[2][PCCAP];
    unsigned int labw[16];            // label-1 bit per global rank
    unsigned int pre1[16];            // excl prefix of label-1 popcounts
    unsigned int kbits[2][8];         // per-class keep bits
    unsigned int kw[16];              // global keep bits
    unsigned int kpre[16];            // excl prefix of keep popcounts
    unsigned short clsrank[CAP];
    float karea[MAXDET]; float kscore[MAXDET]; int klab[MAXDET];
    int cn[2];
    int c1_rel, n_valid, n_sel, fb, s_cnt, cnt_sel, kept_total;
};

__device__ __forceinline__ float read_dim(const void* p) {
    if (p == nullptr) return 800.0f;
    int v = *(const int*)p;
    if (v > 0 && v < 1000000) return (float)v;   // stored as int32
    return *(const float*)p;                      // stored as float32
}

__device__ __forceinline__ int hbin_of(unsigned long long k) {
    int b12 = (int)(k >> 52);
    return min(max(b12 - HB0, 0), NHB - 1);
}

__global__ __launch_bounds__(1024, 1)
void fused_kernel(const float* __restrict__ logits,
                  const float* __restrict__ reg,
                  const float* __restrict__ props,
                  const void* ph, const void* pw,
                  float* __restrict__ out) {
    extern __shared__ unsigned char smem_raw[];
    SM& s = *reinterpret_cast<SM*>(smem_raw);

    const int b    = blockIdx.x;
    const int tid  = threadIdx.x;
    const int lane = tid & 31;
    const int wid  = tid >> 5;
    const unsigned FULL = 0xFFFFFFFFu;
    const float H = read_dim(ph), W = read_dim(pw);
    const float SCL = 4.135166556742356f;   // ln(1000/16)

    if (tid == 0) { s.fb = 0; s.cnt_sel = 0; s.n_sel = 0; }
    if (tid < NHB) s.hist[tid] = 0;
    __syncthreads();   // hist must be zero before Phase A's fused atomics

    // ---- Phase A: prep (softmax + decode + clip + key + fused histogram) ----
    for (int p = tid; p < NP; p += 1024) {
        const float* L = logits + (b * NP + p) * 3;
        float l0 = L[0], l1 = L[1], l2 = L[2];
        float mx = fmaxf(l0, fmaxf(l1, l2));
        float e0 = __expf(l0 - mx), e1 = __expf(l1 - mx), e2 = __expf(l2 - mx);
        float inv = __fdividef(1.0f, e0 + e1 + e2);
        float sc1 = e1 * inv, sc2 = e2 * inv;

        const float4 P = *(const float4*)(props + (b * NP + p) * 4);
        float pw_ = P.z - P.x, ph_ = P.w - P.y;
        float cx = P.x + 0.5f * pw_, cy = P.y + 0.5f * ph_;

        const float4 R1 = *(const float4*)(reg + (b * NP + p) * 12 + 4);
        const float4 R2 = *(const float4*)(reg + (b * NP + p) * 12 + 8);

        #pragma unroll
        for (int cc = 0; cc < 2; cc++) {
            float4 R = cc ? R2 : R1;
            float sc = cc ? sc2 : sc1;
            int   m  = 2 * p + cc;
            float dx = R.x * 0.1f;
            float dy = R.y * 0.1f;
            float dw = fminf(R.z * 0.2f, SCL);
            float dh = fminf(R.w * 0.2f, SCL);
            float pcx = dx * pw_ + cx;
            float pcy = dy * ph_ + cy;
            float nw  = __expf(dw) * pw_;
            float nh  = __expf(dh) * ph_;
            float x1 = fminf(fmaxf(pcx - 0.5f * nw, 0.0f), W);
            float y1 = fminf(fmaxf(pcy - 0.5f * nh, 0.0f), H);
            float x2 = fminf(fmaxf(pcx + 0.5f * nw, 0.0f), W);
            float y2 = fminf(fmaxf(pcy + 0.5f * nh, 0.0f), H);
            bool valid = (sc > 0.05f) && ((x2 - x1) >= 0.01f) && ((y2 - y1) >= 0.01f);
            s.box[m] = make_float4(x1, y1, x2, y2);
            unsigned long long key;
            if (valid) {
                unsigned mono = __float_as_uint(sc) | 0x80000000u;    // sc > 0
                key = (((unsigned long long)(~mono)) << 32) | (unsigned)m;
                atomicAdd(&s.hist[hbin_of(key)], 1u);
            } else {
                key = 0xFFFFFFFF00000000ull | (unsigned)m;            // bin 0xFFF
            }
            s.key[m] = key;
        }
    }
    __syncthreads();

    // ---- Phase B: single-warp cutoff scan over 64 bins ----
    if (tid < 32) {   // 2 bins per lane, ordered scan
        unsigned v0 = s.hist[2 * lane], v1 = s.hist[2 * lane + 1];
        unsigned lsum = v0 + v1;
        unsigned inc = lsum;
        #pragma unroll
        for (int o = 1; o < 32; o <<= 1) {
            unsigned x = __shfl_up_sync(FULL, inc, o);
            if (lane >= o) inc += x;
        }
        unsigned excl = inc - lsum;
        unsigned total = __shfl_sync(FULL, inc, 31);
        bool cross = ((int)excl < TSEL) && ((int)(excl + lsum) >= TSEL);
        unsigned mb = __ballot_sync(FULL, cross);
        if (lane == 0) s.n_valid = (int)total;
        if (mb == 0) {
            if (lane == 0) { s.c1_rel = NHB - 1; s.n_sel = (int)total; }  // take all valid
        } else {
            int src = __ffs(mb) - 1;
            if (lane == src) {
                int rel, incl;
                if ((int)excl + (int)v0 >= TSEL) { rel = 2 * src;     incl = (int)excl + (int)v0; }
                else                             { rel = 2 * src + 1; incl = (int)excl + (int)lsum; }
                if (incl > CAP) s.fb = 1;                      // fat cutoff bin -> fallback
                else            { s.c1_rel = rel; s.n_sel = incl; }
            }
        }
    }
    __syncthreads();

    const int n_sel = s.n_sel;
    const int c1r   = s.c1_rel;

    // ---- compact selected keys (unordered) ----
    if (!s.fb) {
        for (int m = tid; m < MM; m += 1024) {
            unsigned long long k = s.key[m];
            if ((int)(k >> 52) != 0xFFF && hbin_of(k) <= c1r) {
                int pos = atomicAdd(&s.cnt_sel, 1);
                if (pos < CAP) s.selkey[pos] = k;
            }
        }
    }
    __syncthreads();
    for (int t = tid; t < CAP; t += 1024)
        if (t >= n_sel) s.selkey[t] = 0xFFFFFFFFFFFFF000ull + (unsigned)t;
    __syncthreads();

    // ---- Phase C: rank sort, 4 threads per element (quads lane-aligned) ----
    const int n_pad = (n_sel + 31) & ~31;
    if (n_pad <= 256) {
        if (tid < 4 * n_pad) {
            int e = tid >> 2, q = tid & 3;
            unsigned long long k = s.selkey[e];
            int qn = n_pad >> 2;
            int j0 = q * qn, j1 = j0 + qn;
            int r = 0;
            #pragma unroll 8
            for (int j = j0; j < j1; j++) r += (s.selkey[j] < k);
            r += __shfl_xor_sync(FULL, r, 1);
            r += __shfl_xor_sync(FULL, r, 2);
            if (q == 0) s.skey[r] = k;
        }
    } else {
        if (tid < 2 * n_pad) {
            int e = tid >> 1, half = tid & 1;
            unsigned long long k = s.selkey[e];
            int j0 = half ? (n_pad >> 1) : 0;
            int j1 = half ? n_pad : (n_pad >> 1);
            int r = 0;
            #pragma unroll 8
            for (int j = j0; j < j1; j++) r += (s.selkey[j] < k);
            r += __shfl_xor_sync(FULL, r, 1);
            if (!half) s.skey[r] = k;
        }
    }
    __syncthreads();

    // ---- Phase D: gather + per-class partition ----
    bool act = false; int lab = 0; float4 bb = make_float4(0.f, 0.f, 0.f, 0.f);
    if (tid < 512) {
        act = (tid < n_sel);
        if (act) {
            int idx = (int)(unsigned)s.skey[tid];
            lab = idx & 1;
            bb = s.box[idx];
            s.sbox[tid] = bb;
        }
        unsigned bal = __ballot_sync(FULL, act && lab);
        if (lane == 0) s.labw[wid] = bal;
    }
    __syncthreads();
    if (tid < 32) {
        unsigned c = (lane < 16) ? __popc(s.labw[lane]) : 0;
        unsigned inc = c;
        #pragma unroll
        for (int o = 1; o < 32; o <<= 1) {
            unsigned x = __shfl_up_sync(FULL, inc, o);
            if (lane >= o) inc += x;
        }
        if (lane < 16) s.pre1[lane] = inc - c;
        unsigned cn1 = __shfl_sync(FULL, inc, 15);
        if (lane == 0) {
            s.cn[1] = (int)cn1;
            s.cn[0] = n_sel - (int)cn1;
            if (s.cn[0] > PCCAP || s.cn[1] > PCCAP) s.fb = 1;
        }
    }
    __syncthreads();
    if (tid < 512 && act) {
        unsigned low = (1u << lane) - 1u;
        int c1below = (int)s.pre1[wid] + __popc(s.labw[wid] & low);
        int r = lab ? c1below : (tid - c1below);
        s.clsrank[tid] = (unsigned short)r;
        if (r < PCCAP) {
            s.cbox[lab][r]  = bb;
            s.carea[lab][r] = (bb.z - bb.x) * (bb.w - bb.y);
        }
    }
    // zero-pad per-class tails (disjoint addresses from scatter above)
    for (int u = tid; u < 2 * PCCAP; u += 1024) {
        int c = u >> 8, r = u & (PCCAP - 1);
        if (r >= min(s.cn[c], PCCAP)) {
            s.cbox[c][r] = make_float4(0.f, 0.f, 0.f, 0.f);
            s.carea[c][r] = 0.f;
        }
    }
    __syncthreads();

    // ---- Phase E: per-class suppression bitmask ----
    for (int u = tid; u < 2 * PCCAP * 8; u += 1024) {
        int c = u >> 11, i = (u >> 3) & (PCCAP - 1), w = u & 7;
        unsigned bits = 0;
        int nc_ = s.cn[c];
        if (i < nc_ && w >= (i >> 5) && (w << 5) < nc_) {
            float4 bi = s.cbox[c][i];
            float  ai = s.carea[c][i];
            int j0 = w << 5;
            #pragma unroll
            for (int l = 0; l < 32; l++) {
                int j = j0 + l;
                float4 bj = s.cbox[c][j];
                float iw = fminf(bi.z, bj.z) - fmaxf(bi.x, bj.x);
                float ih = fminf(bi.w, bj.w) - fmaxf(bi.y, bj.y);
                iw = fmaxf(iw, 0.0f); ih = fmaxf(ih, 0.0f);
                float inter = iw * ih;
                bool sp = (j > i) && (2.0f * inter > ai + s.carea[c][j] - inter + 1e-7f);
                bits |= (sp ? (1u << l) : 0u);
            }
        }
        s.mask[c][i][w] = bits;
    }
    __syncthreads();

    // ---- Phase F: per-class greedy resolution (warps 0 and 1 in parallel) ----
    if (wid < 2) {
        int c = wid;
        int nc_ = min(s.cn[c], PCCAP);
        unsigned removed = 0, kb = 0;
        int cnt = 0;
        for (int i = 0; i < nc_; i++) {
            unsigned rw = __shfl_sync(FULL, removed, i >> 5);
            if (!((rw >> (i & 31)) & 1u)) {
                if (lane == (i >> 5)) kb |= 1u << (i & 31);
                cnt++;
                if (lane < 8) removed |= s.mask[c][i][lane];
                if (cnt == MAXDET) break;
            }
        }
        if (lane < 8) s.kbits[c][lane] = kb;
    }
    __syncthreads();

    // ---- Phase G: merge kept flags back to global order ----
    bool kflag = false;
    if (tid < 512) {
        if (act) {
            int r = s.clsrank[tid];
            kflag = (s.kbits[lab][r >> 5] >> (r & 31)) & 1u;
        }
        unsigned bal = __ballot_sync(FULL, kflag);
        if (lane == 0) s.kw[wid] = bal;
    }
    __syncthreads();
    if (tid < 32) {
        unsigned c = (lane < 16) ? __popc(s.kw[lane]) : 0;
        unsigned inc = c;
        #pragma unroll
        for (int o = 1; o < 32; o <<= 1) {
            unsigned x = __shfl_up_sync(FULL, inc, o);
            if (lane >= o) inc += x;
        }
        if (lane < 16) s.kpre[lane] = inc - c;
        unsigned tot = __shfl_sync(FULL, inc, 15);
        if (lane == 0) {
            s.kept_total = (int)tot;
            if ((int)tot < MAXDET && s.n_valid > n_sel) s.fb = 1;  // prefix exhausted
        }
    }
    __syncthreads();

    float* oB = out;                              // [B,100,4]
    float* oS = out + BD * MAXDET * 4;            // [B,100]
    float* oL = oS + BD * MAXDET;                 // [B,100]
    float* oK = oL + BD * MAXDET;                 // [B,100]

    if (!s.fb) {
        for (int j = tid; j < MAXDET; j += 1024) {
            int base = (b * MAXDET + j) * 4;
            oB[base + 0] = 0.f; oB[base + 1] = 0.f; oB[base + 2] = 0.f; oB[base + 3] = 0.f;
            oS[b * MAXDET + j] = 0.f;
            oL[b * MAXDET + j] = 0.f;
            oK[b * MAXDET + j] = 0.f;
        }
        __syncthreads();
        if (tid < 512 && kflag) {
            unsigned low = (1u << lane) - 1u;
            int pos = (int)s.kpre[wid] + __popc(s.kw[wid] & low);
            if (pos < MAXDET) {
                unsigned long long key = s.skey[tid];
                float sc = __uint_as_float((~(unsigned)(key >> 32)) & 0x7FFFFFFFu);
                float4 bx = s.sbox[tid];
                int base = (b * MAXDET + pos) * 4;
                oB[base + 0] = bx.x; oB[base + 1] = bx.y;
                oB[base + 2] = bx.z; oB[base + 3] = bx.w;
                oS[b * MAXDET + pos] = sc;
                oL[b * MAXDET + pos] = (float)(lab + 1);
                oK[b * MAXDET + pos] = 1.0f;
            }
        }
        return;
    }

    // ================= FALLBACK: full bitonic sort + warp NMS =================
    #pragma unroll 1
    for (int k = 2; k <= MM; k <<= 1) {
        #pragma unroll 1
        for (int j = k >> 1; j > 0; j >>= 1) {
            #pragma unroll
            for (int q = 0; q < 2; q++) {
                int p = tid + q * 1024;
                int i = ((p & ~(j - 1)) << 1) | (p & (j - 1));
                int l = i | j;
                bool up = ((i & k) == 0);
                unsigned long long a = s.key[i], c = s.key[l];
                if ((a > c) == up) { s.key[i] = c; s.key[l] = a; }
            }
            __syncthreads();
        }
    }
    for (int t = tid; t < PRE; t += 1024) {
        int idx = (int)(unsigned)s.key[t];
        s.sbox[t] = s.box[idx];
    }
    __syncthreads();

    if (tid < 32) {
        int cnt = 0;
        for (int t = 0; t < MM; t++) {
            unsigned long long key = s.key[t];
            unsigned hi = (unsigned)(key >> 32);
            if (hi == 0xFFFFFFFFu) break;
            int idx = (int)(unsigned)key;
            int lb = idx & 1;
            float sc = __uint_as_float((~hi) & 0x7FFFFFFFu);
            float4 bc = (t < PRE) ? s.sbox[t] : s.box[idx];
            float area = (bc.z - bc.x) * (bc.w - bc.y);
            bool sup = false;
            for (int j = lane; j < cnt; j += 32) {
                if (s.klab[j] == lb) {
                    float4 kb = s.kbox[j];
                    float iw = fminf(bc.z, kb.z) - fmaxf(bc.x, kb.x);
                    float ih = fminf(bc.w, kb.w) - fmaxf(bc.y, kb.y);
                    iw = fmaxf(iw, 0.0f); ih = fmaxf(ih, 0.0f);
                    float inter = iw * ih;
                    if (2.0f * inter > area + s.karea[j] - inter + 1e-7f) sup = true;
                }
            }
            if (__ballot_sync(FULL, sup) == 0u) {
                if (lane == 0) {
                    s.kbox[cnt] = bc; s.karea[cnt] = area;
                    s.kscore[cnt] = sc; s.klab[cnt] = lb;
                }
                cnt++;
                __syncwarp();
                if (cnt == MAXDET) break;
            }
        }
        if (lane == 0) s.s_cnt = cnt;
    }
    __syncthreads();

    int cnt = s.s_cnt;
    for (int j = tid; j < MAXDET; j += 1024) {
        bool k = (j < cnt);
        float4 bc = k ? s.kbox[j] : make_float4(0.f, 0.f, 0.f, 0.f);
        int base = (b * MAXDET + j) * 4;
        oB[base + 0] = bc.x; oB[base + 1] = bc.y;
        oB[base + 2] = bc.z; oB[base + 3] = bc.w;
        oS[b * MAXDET + j] = k ? s.kscore[j] : 0.0f;
        oL[b * MAXDET + j] = k ? (float)(s.klab[j] + 1) : 0.0f;
        oK[b * MAXDET + j] = k ? 1.0f : 0.0f;
    }
}

// ---------------------------------------------------------------------------
extern "C" void kernel_launch(void* const* d_in, const int* in_sizes, int n_in,
                              void* d_out, int out_size) {
    const float* logits = nullptr;
    const float* reg    = nullptr;
    const float* props  = nullptr;
    const void*  dims[2] = {nullptr, nullptr};
    int nd = 0;
    for (int i = 0; i < n_in; i++) {
        int sz = in_sizes[i];
        if      (sz == BD * NP * 3)  logits = (const float*)d_in[i];
        else if (sz == BD * NP * 12) reg    = (const float*)d_in[i];
        else if (sz == BD * NP * 4)  props  = (const float*)d_in[i];
        else if (sz == 1 && nd < 2)  dims[nd++] = d_in[i];
    }

    const int smem_bytes = (int)sizeof(SM);
    cudaFuncSetAttribute(fused_kernel, cudaFuncAttributeMaxDynamicSharedMemorySize, smem_bytes);
    fused_kernel<<<BD, 1024, smem_bytes>>>(logits, reg, props, dims[0], dims[1], (float*)d_out);
}

// round 15
// speedup vs baseline: 1.3208x; 1.2795x over previous
#include <cuda_runtime.h>

// Problem shapes (fixed by setup_inputs): B=4, N=2048, C=3
#define BD 4
#define NP 2048
#define MM 4096          // N * (C-1) candidates per image
#define MAXDET 100
#define CAP 512          // max selected candidates (global prefix)
#define PCCAP 256        // max per-class selected candidates
#define TSEL 160         // selection target (> ~110 consumed by NMS)
#define PRE 512          // fallback: sorted boxes pre-gathered
#define HB0 0x400        // first histogram bin (12-bit key bin space)
#define NHB 64           // histogram bins

struct __align__(16) SM {
    float4 box[MM];                   // all candidate boxes (smem-resident)
    unsigned long long key[MM];       // all 4096 keys (intact for fallback)
    unsigned long long selkey[CAP];   // selected (unordered, padded)
    unsigned long long skey[CAP];     // selected (sorted)
    float4 sbox[CAP];                 // boxes in global sorted order
    float4 cbox[2][PCCAP];            // per-class boxes (score order, zero-padded)
    float4 kbox[MAXDET];              // fallback kept boxes
    unsigned int hist[NHB];
    unsigned int mask[2][PCCAP][8];   // per-class suppression bitmask
    float carea[2][PCCAP];
    unsigned int labw[16];            // label-1 bit per global rank
    unsigned int pre1[16];            // excl prefix of label-1 popcounts
    unsigned int kbits[2][8];         // per-class keep bits
    unsigned int kw[16];              // global keep bits
    unsigned int kpre[16];            // excl prefix of keep popcounts
    unsigned short clsrank[CAP];
    float karea[MAXDET]; float kscore[MAXDET]; int klab[MAXDET];
    int cn[2];
    int c1_rel, n_valid, n_sel, fb, s_cnt, cnt_sel, kept_total;
};

__device__ __forceinline__ float read_dim(const void* p) {
    if (p == nullptr) return 800.0f;
    int v = *(const int*)p;
    if (v > 0 && v < 1000000) return (float)v;   // stored as int32
    return *(const float*)p;                      // stored as float32
}

__device__ __forceinline__ int hbin_of(unsigned long long k) {
    int b12 = (int)(k >> 52);
    return min(max(b12 - HB0, 0), NHB - 1);
}

__global__ __launch_bounds__(1024, 1)
void fused_kernel(const float* __restrict__ logits,
                  const float* __restrict__ reg,
                  const float* __restrict__ props,
                  const void* ph, const void* pw,
                  float* __restrict__ out) {
    extern __shared__ unsigned char smem_raw[];
    SM& s = *reinterpret_cast<SM*>(smem_raw);

    const int b    = blockIdx.x;
    const int tid  = threadIdx.x;
    const int lane = tid & 31;
    const int wid  = tid >> 5;
    const unsigned FULL = 0xFFFFFFFFu;
    const float H = read_dim(ph), W = read_dim(pw);
    const float SCL = 4.135166556742356f;   // ln(1000/16)

    if (tid == 0) { s.fb = 0; s.cnt_sel = 0; s.n_sel = 0; }
    if (tid < NHB) s.hist[tid] = 0;
    __syncthreads();   // hist must be zero before Phase A's fused atomics

    // ---- Phase A: prep (softmax + decode + clip + key + fused histogram) ----
    for (int p = tid; p < NP; p += 1024) {
        const float* L = logits + (b * NP + p) * 3;
        float l0 = L[0], l1 = L[1], l2 = L[2];
        float mx = fmaxf(l0, fmaxf(l1, l2));
        float e0 = __expf(l0 - mx), e1 = __expf(l1 - mx), e2 = __expf(l2 - mx);
        float inv = __fdividef(1.0f, e0 + e1 + e2);
        float sc1 = e1 * inv, sc2 = e2 * inv;

        const float4 P = *(const float4*)(props + (b * NP + p) * 4);
        float pw_ = P.z - P.x, ph_ = P.w - P.y;
        float cx = P.x + 0.5f * pw_, cy = P.y + 0.5f * ph_;

        const float4 R1 = *(const float4*)(reg + (b * NP + p) * 12 + 4);
        const float4 R2 = *(const float4*)(reg + (b * NP + p) * 12 + 8);

        #pragma unroll
        for (int cc = 0; cc < 2; cc++) {
            float4 R = cc ? R2 : R1;
            float sc = cc ? sc2 : sc1;
            int   m  = 2 * p + cc;
            float dx = R.x * 0.1f;
            float dy = R.y * 0.1f;
            float dw = fminf(R.z * 0.2f, SCL);
            float dh = fminf(R.w * 0.2f, SCL);
            float pcx = dx * pw_ + cx;
            float pcy = dy * ph_ + cy;
            float nw  = __expf(dw) * pw_;
            float nh  = __expf(dh) * ph_;
            float x1 = fminf(fmaxf(pcx - 0.5f * nw, 0.0f), W);
            float y1 = fminf(fmaxf(pcy - 0.5f * nh, 0.0f), H);
            float x2 = fminf(fmaxf(pcx + 0.5f * nw, 0.0f), W);
            float y2 = fminf(fmaxf(pcy + 0.5f * nh, 0.0f), H);
            bool valid = (sc > 0.05f) && ((x2 - x1) >= 0.01f) && ((y2 - y1) >= 0.01f);
            s.box[m] = make_float4(x1, y1, x2, y2);
            unsigned long long key;
            if (valid) {
                unsigned mono = __float_as_uint(sc) | 0x80000000u;    // sc > 0
                key = (((unsigned long long)(~mono)) << 32) | (unsigned)m;
                atomicAdd(&s.hist[hbin_of(key)], 1u);
            } else {
                key = 0xFFFFFFFF00000000ull | (unsigned)m;            // bin 0xFFF
            }
            s.key[m] = key;
        }
    }
    __syncthreads();

    // ---- Phase B: single-warp cutoff scan over 64 bins ----
    if (tid < 32) {   // 2 bins per lane, ordered scan
        unsigned v0 = s.hist[2 * lane], v1 = s.hist[2 * lane + 1];
        unsigned lsum = v0 + v1;
        unsigned inc = lsum;
        #pragma unroll
        for (int o = 1; o < 32; o <<= 1) {
            unsigned x = __shfl_up_sync(FULL, inc, o);
            if (lane >= o) inc += x;
        }
        unsigned excl = inc - lsum;
        unsigned total = __shfl_sync(FULL, inc, 31);
        bool cross = ((int)excl < TSEL) && ((int)(excl + lsum) >= TSEL);
        unsigned mb = __ballot_sync(FULL, cross);
        if (lane == 0) s.n_valid = (int)total;
        if (mb == 0) {
            if (lane == 0) { s.c1_rel = NHB - 1; s.n_sel = (int)total; }  // take all valid
        } else {
            int src = __ffs(mb) - 1;
            if (lane == src) {
                int rel, incl;
                if ((int)excl + (int)v0 >= TSEL) { rel = 2 * src;     incl = (int)excl + (int)v0; }
                else                             { rel = 2 * src + 1; incl = (int)excl + (int)lsum; }
                if (incl > CAP) s.fb = 1;                      // fat cutoff bin -> fallback
                else            { s.c1_rel = rel; s.n_sel = incl; }
            }
        }
    }
    __syncthreads();

    const int n_sel = s.n_sel;
    const int c1r   = s.c1_rel;

    // ---- compact selected keys (unordered) ----
    if (!s.fb) {
        for (int m = tid; m < MM; m += 1024) {
            unsigned long long k = s.key[m];
            if ((int)(k >> 52) != 0xFFF && hbin_of(k) <= c1r) {
                int pos = atomicAdd(&s.cnt_sel, 1);
                if (pos < CAP) s.selkey[pos] = k;
            }
        }
    }
    __syncthreads();
    for (int t = tid; t < CAP; t += 1024)
        if (t >= n_sel) s.selkey[t] = 0xFFFFFFFFFFFFF000ull + (unsigned)t;
    __syncthreads();

    // ---- Phase C: rank sort, 2 threads per element (pairs are warp-aligned) ----
    const int n_pad = (n_sel + 31) & ~31;
    if (tid < 2 * n_pad) {
        int e = tid >> 1, half = tid & 1;
        unsigned long long k = s.selkey[e];
        int j0 = half ? (n_pad >> 1) : 0;
        int j1 = half ? n_pad : (n_pad >> 1);
        int r = 0;
        #pragma unroll 8
        for (int j = j0; j < j1; j++) r += (s.selkey[j] < k);
        r += __shfl_xor_sync(FULL, r, 1);
        if (!half) s.skey[r] = k;
    }
    __syncthreads();

    // ---- Phase D: gather + per-class partition ----
    bool act = false; int lab = 0; float4 bb = make_float4(0.f, 0.f, 0.f, 0.f);
    if (tid < 512) {
        act = (tid < n_sel);
        if (act) {
            int idx = (int)(unsigned)s.skey[tid];
            lab = idx & 1;
            bb = s.box[idx];
            s.sbox[tid] = bb;
        }
        unsigned bal = __ballot_sync(FULL, act && lab);
        if (lane == 0) s.labw[wid] = bal;
    }
    __syncthreads();
    if (tid < 32) {
        unsigned c = (lane < 16) ? __popc(s.labw[lane]) : 0;
        unsigned inc = c;
        #pragma unroll
        for (int o = 1; o < 32; o <<= 1) {
            unsigned x = __shfl_up_sync(FULL, inc, o);
            if (lane >= o) inc += x;
        }
        if (lane < 16) s.pre1[lane] = inc - c;
        unsigned cn1 = __shfl_sync(FULL, inc, 15);
        if (lane == 0) {
            s.cn[1] = (int)cn1;
            s.cn[0] = n_sel - (int)cn1;
            if (s.cn[0] > PCCAP || s.cn[1] > PCCAP) s.fb = 1;
        }
    }
    __syncthreads();
    if (tid < 512 && act) {
        unsigned low = (1u << lane) - 1u;
        int c1below = (int)s.pre1[wid] + __popc(s.labw[wid] & low);
        int r = lab ? c1below : (tid - c1below);
        s.clsrank[tid] = (unsigned short)r;
        if (r < PCCAP) {
            s.cbox[lab][r]  = bb;
            s.carea[lab][r] = (bb.z - bb.x) * (bb.w - bb.y);
        }
    }
    // zero-pad per-class tails (disjoint addresses from scatter above)
    for (int u = tid; u < 2 * PCCAP; u += 1024) {
        int c = u >> 8, r = u & (PCCAP - 1);
        if (r >= min(s.cn[c], PCCAP)) {
            s.cbox[c][r] = make_float4(0.f, 0.f, 0.f, 0.f);
            s.carea[c][r] = 0.f;
        }
    }
    __syncthreads();

    // ---- Phase E: per-class suppression bitmask ----
    for (int u = tid; u < 2 * PCCAP * 8; u += 1024) {
        int c = u >> 11, i = (u >> 3) & (PCCAP - 1), w = u & 7;
        unsigned bits = 0;
        int nc_ = s.cn[c];
        if (i < nc_ && w >= (i >> 5) && (w << 5) < nc_) {
            float4 bi = s.cbox[c][i];
            float  ai = s.carea[c][i];
            int j0 = w << 5;
            #pragma unroll
            for (int l = 0; l < 32; l++) {
                int j = j0 + l;
                float4 bj = s.cbox[c][j];
                float iw = fminf(bi.z, bj.z) - fmaxf(bi.x, bj.x);
                float ih = fminf(bi.w, bj.w) - fmaxf(bi.y, bj.y);
                iw = fmaxf(iw, 0.0f); ih = fmaxf(ih, 0.0f);
                float inter = iw * ih;
                bool sp = (j > i) && (2.0f * inter > ai + s.carea[c][j] - inter + 1e-7f);
                bits |= (sp ? (1u << l) : 0u);
            }
        }
        s.mask[c][i][w] = bits;
    }
    __syncthreads();

    // ---- Phase F: per-class greedy resolution (warps 0 and 1 in parallel) ----
    if (wid < 2) {
        int c = wid;
        int nc_ = min(s.cn[c], PCCAP);
        unsigned removed = 0, kb = 0;
        int cnt = 0;
        for (int i = 0; i < nc_; i++) {
            unsigned rw = __shfl_sync(FULL, removed, i >> 5);
            if (!((rw >> (i & 31)) & 1u)) {
                if (lane == (i >> 5)) kb |= 1u << (i & 31);
                cnt++;
                if (lane < 8) removed |= s.mask[c][i][lane];
                if (cnt == MAXDET) break;
            }
        }
        if (lane < 8) s.kbits[c][lane] = kb;
    }
    __syncthreads();

    // ---- Phase G: merge kept flags back to global order ----
    bool kflag = false;
    if (tid < 512) {
        if (act) {
            int r = s.clsrank[tid];
            kflag = (s.kbits[lab][r >> 5] >> (r & 31)) & 1u;
        }
        unsigned bal = __ballot_sync(FULL, kflag);
        if (lane == 0) s.kw[wid] = bal;
    }
    __syncthreads();
    if (tid < 32) {
        unsigned c = (lane < 16) ? __popc(s.kw[lane]) : 0;
        unsigned inc = c;
        #pragma unroll
        for (int o = 1; o < 32; o <<= 1) {
            unsigned x = __shfl_up_sync(FULL, inc, o);
            if (lane >= o) inc += x;
        }
        if (lane < 16) s.kpre[lane] = inc - c;
        unsigned tot = __shfl_sync(FULL, inc, 15);
        if (lane == 0) {
            s.kept_total = (int)tot;
            if ((int)tot < MAXDET && s.n_valid > n_sel) s.fb = 1;  // prefix exhausted
        }
    }
    __syncthreads();

    float* oB = out;                              // [B,100,4]
    float* oS = out + BD * MAXDET * 4;            // [B,100]
    float* oL = oS + BD * MAXDET;                 // [B,100]
    float* oK = oL + BD * MAXDET;                 // [B,100]

    if (!s.fb) {
        for (int j = tid; j < MAXDET; j += 1024) {
            int base = (b * MAXDET + j) * 4;
            oB[base + 0] = 0.f; oB[base + 1] = 0.f; oB[base + 2] = 0.f; oB[base + 3] = 0.f;
            oS[b * MAXDET + j] = 0.f;
            oL[b * MAXDET + j] = 0.f;
            oK[b * MAXDET + j] = 0.f;
        }
        __syncthreads();
        if (tid < 512 && kflag) {
            unsigned low = (1u << lane) - 1u;
            int pos = (int)s.kpre[wid] + __popc(s.kw[wid] & low);
            if (pos < MAXDET) {
                unsigned long long key = s.skey[tid];
                float sc = __uint_as_float((~(unsigned)(key >> 32)) & 0x7FFFFFFFu);
                float4 bx = s.sbox[tid];
                int base = (b * MAXDET + pos) * 4;
                oB[base + 0] = bx.x; oB[base + 1] = bx.y;
                oB[base + 2] = bx.z; oB[base + 3] = bx.w;
                oS[b * MAXDET + pos] = sc;
                oL[b * MAXDET + pos] = (float)(lab + 1);
                oK[b * MAXDET + pos] = 1.0f;
            }
        }
        return;
    }

    // ================= FALLBACK: full bitonic sort + warp NMS =================
    #pragma unroll 1
    for (int k = 2; k <= MM; k <<= 1) {
        #pragma unroll 1
        for (int j = k >> 1; j > 0; j >>= 1) {
            #pragma unroll
            for (int q = 0; q < 2; q++) {
                int p = tid + q * 1024;
                int i = ((p & ~(j - 1)) << 1) | (p & (j - 1));
                int l = i | j;
                bool up = ((i & k) == 0);
                unsigned long long a = s.key[i], c = s.key[l];
                if ((a > c) == up) { s.key[i] = c; s.key[l] = a; }
            }
            __syncthreads();
        }
    }
    for (int t = tid; t < PRE; t += 1024) {
        int idx = (int)(unsigned)s.key[t];
        s.sbox[t] = s.box[idx];
    }
    __syncthreads();

    if (tid < 32) {
        int cnt = 0;
        for (int t = 0; t < MM; t++) {
            unsigned long long key = s.key[t];
            unsigned hi = (unsigned)(key >> 32);
            if (hi == 0xFFFFFFFFu) break;
            int idx = (int)(unsigned)key;
            int lb = idx & 1;
            float sc = __uint_as_float((~hi) & 0x7FFFFFFFu);
            float4 bc = (t < PRE) ? s.sbox[t] : s.box[idx];
            float area = (bc.z - bc.x) * (bc.w - bc.y);
            bool sup = false;
            for (int j = lane; j < cnt; j += 32) {
                if (s.klab[j] == lb) {
                    float4 kb = s.kbox[j];
                    float iw = fminf(bc.z, kb.z) - fmaxf(bc.x, kb.x);
                    float ih = fminf(bc.w, kb.w) - fmaxf(bc.y, kb.y);
                    iw = fmaxf(iw, 0.0f); ih = fmaxf(ih, 0.0f);
                    float inter = iw * ih;
                    if (2.0f * inter > area + s.karea[j] - inter + 1e-7f) sup = true;
                }
            }
            if (__ballot_sync(FULL, sup) == 0u) {
                if (lane == 0) {
                    s.kbox[cnt] = bc; s.karea[cnt] = area;
                    s.kscore[cnt] = sc; s.klab[cnt] = lb;
                }
                cnt++;
                __syncwarp();
                if (cnt == MAXDET) break;
            }
        }
        if (lane == 0) s.s_cnt = cnt;
    }
    __syncthreads();

    int cnt = s.s_cnt;
    for (int j = tid; j < MAXDET; j += 1024) {
        bool k = (j < cnt);
        float4 bc = k ? s.kbox[j] : make_float4(0.f, 0.f, 0.f, 0.f);
        int base = (b * MAXDET + j) * 4;
        oB[base + 0] = bc.x; oB[base + 1] = bc.y;
        oB[base + 2] = bc.z; oB[base + 3] = bc.w;
        oS[b * MAXDET + j] = k ? s.kscore[j] : 0.0f;
        oL[b * MAXDET + j] = k ? (float)(s.klab[j] + 1) : 0.0f;
        oK[b * MAXDET + j] = k ? 1.0f : 0.0f;
    }
}

// ---------------------------------------------------------------------------
extern "C" void kernel_launch(void* const* d_in, const int* in_sizes, int n_in,
                              void* d_out, int out_size) {
    const float* logits = nullptr;
    const float* reg    = nullptr;
    const float* props  = nullptr;
    const void*  dims[2] = {nullptr, nullptr};
    int nd = 0;
    for (int i = 0; i < n_in; i++) {
        int sz = in_sizes[i];
        if      (sz == BD * NP * 3)  logits = (const float*)d_in[i];
        else if (sz == BD * NP * 12) reg    = (const float*)d_in[i];
        else if (sz == BD * NP * 4)  props  = (const float*)d_in[i];
        else if (sz == 1 && nd < 2)  dims[nd++] = d_in[i];
    }

    const int smem_bytes = (int)sizeof(SM);
    cudaFuncSetAttribute(fused_kernel, cudaFuncAttributeMaxDynamicSharedMemorySize, smem_bytes);
    fused_kernel<<<BD, 1024, smem_bytes>>>(logits, reg, props, dims[0], dims[1], (float*)d_out);
}

// round 16
// speedup vs baseline: 1.3223x; 1.0012x over previous
#include <cuda_runtime.h>

// Problem shapes (fixed by setup_inputs): B=4, N=2048, C=3
#define BD 4
#define NP 2048
#define MM 4096          // N * (C-1) candidates per image
#define MAXDET 100
#define CAP 512          // max selected candidates (global prefix)
#define PCCAP 256        // max per-class selected candidates
#define TSEL 160         // selection target (> ~110 consumed by NMS)
#define PRE 512          // fallback: sorted boxes pre-gathered
#define HB0 0x400        // first histogram bin (12-bit key bin space)
#define NHB 64           // histogram bins

struct __align__(16) SM {
    float4 box[MM];                   // all candidate boxes (smem-resident)
    unsigned long long key[MM];       // all 4096 keys (intact for fallback)
    unsigned long long selkey[CAP];   // selected (unordered, padded)
    unsigned long long skey[CAP];     // selected (sorted)
    float4 sbox[CAP];                 // boxes in global sorted order
    float4 cbox[2][PCCAP];            // per-class boxes (score order, zero-padded)
    float4 kbox[MAXDET];              // fallback kept boxes
    unsigned int hist[NHB];
    unsigned int mask[2][PCCAP][8];   // per-class suppression bitmask
    float carea[2][PCCAP];
    unsigned int labw[16];            // label-1 bit per global rank
    unsigned int pre1[16];            // excl prefix of label-1 popcounts
    unsigned int kbits[2][8];         // per-class keep bits
    unsigned int kw[16];              // global keep bits
    unsigned int kpre[16];            // excl prefix of keep popcounts
    unsigned short clsrank[CAP];
    float karea[MAXDET]; float kscore[MAXDET]; int klab[MAXDET];
    int cn[2];
    int c1_rel, n_valid, n_sel, fb, s_cnt, cnt_sel, kept_total;
};

__device__ __forceinline__ float read_dim(const void* p) {
    if (p == nullptr) return 800.0f;
    int v = *(const int*)p;
    if (v > 0 && v < 1000000) return (float)v;   // stored as int32
    return *(const float*)p;                      // stored as float32
}

__device__ __forceinline__ int hbin_of(unsigned long long k) {
    int b12 = (int)(k >> 52);
    return min(max(b12 - HB0, 0), NHB - 1);
}

__global__ __launch_bounds__(1024, 1)
void fused_kernel(const float* __restrict__ logits,
                  const float* __restrict__ reg,
                  const float* __restrict__ props,
                  const void* ph, const void* pw,
                  float* __restrict__ out) {
    extern __shared__ unsigned char smem_raw[];
    SM& s = *reinterpret_cast<SM*>(smem_raw);

    const int b    = blockIdx.x;
    const int tid  = threadIdx.x;
    const int lane = tid & 31;
    const int wid  = tid >> 5;
    const unsigned FULL = 0xFFFFFFFFu;
    const float H = read_dim(ph), W = read_dim(pw);
    const float SCL = 4.135166556742356f;   // ln(1000/16)

    if (tid == 0) { s.fb = 0; s.cnt_sel = 0; s.n_sel = 0; }
    if (tid < NHB) s.hist[tid] = 0;
    // sentinel pre-fill (compaction overwrites [0, n_sel); tail stays sentinel)
    for (int t = tid; t < CAP; t += 1024)
        s.selkey[t] = 0xFFFFFFFFFFFFF000ull + (unsigned)t;
    __syncthreads();   // hist/selkey must be ready before Phase A + compaction

    // ---- Phase A: prep (softmax + decode + clip + key + fused histogram) ----
    for (int p = tid; p < NP; p += 1024) {
        const float* L = logits + (b * NP + p) * 3;
        float l0 = L[0], l1 = L[1], l2 = L[2];
        float mx = fmaxf(l0, fmaxf(l1, l2));
        float e0 = __expf(l0 - mx), e1 = __expf(l1 - mx), e2 = __expf(l2 - mx);
        float inv = __fdividef(1.0f, e0 + e1 + e2);
        float sc1 = e1 * inv, sc2 = e2 * inv;

        const float4 P = *(const float4*)(props + (b * NP + p) * 4);
        float pw_ = P.z - P.x, ph_ = P.w - P.y;
        float cx = P.x + 0.5f * pw_, cy = P.y + 0.5f * ph_;

        const float4 R1 = *(const float4*)(reg + (b * NP + p) * 12 + 4);
        const float4 R2 = *(const float4*)(reg + (b * NP + p) * 12 + 8);

        #pragma unroll
        for (int cc = 0; cc < 2; cc++) {
            float4 R = cc ? R2 : R1;
            float sc = cc ? sc2 : sc1;
            int   m  = 2 * p + cc;
            float dx = R.x * 0.1f;
            float dy = R.y * 0.1f;
            float dw = fminf(R.z * 0.2f, SCL);
            float dh = fminf(R.w * 0.2f, SCL);
            float pcx = dx * pw_ + cx;
            float pcy = dy * ph_ + cy;
            float nw  = __expf(dw) * pw_;
            float nh  = __expf(dh) * ph_;
            float x1 = fminf(fmaxf(pcx - 0.5f * nw, 0.0f), W);
            float y1 = fminf(fmaxf(pcy - 0.5f * nh, 0.0f), H);
            float x2 = fminf(fmaxf(pcx + 0.5f * nw, 0.0f), W);
            float y2 = fminf(fmaxf(pcy + 0.5f * nh, 0.0f), H);
            bool valid = (sc > 0.05f) && ((x2 - x1) >= 0.01f) && ((y2 - y1) >= 0.01f);
            s.box[m] = make_float4(x1, y1, x2, y2);
            unsigned long long key;
            if (valid) {
                unsigned mono = __float_as_uint(sc) | 0x80000000u;    // sc > 0
                key = (((unsigned long long)(~mono)) << 32) | (unsigned)m;
                atomicAdd(&s.hist[hbin_of(key)], 1u);
            } else {
                key = 0xFFFFFFFF00000000ull | (unsigned)m;            // bin 0xFFF
            }
            s.key[m] = key;
        }
    }
    __syncthreads();

    // ---- Phase B: single-warp cutoff scan over 64 bins ----
    if (tid < 32) {   // 2 bins per lane, ordered scan
        unsigned v0 = s.hist[2 * lane], v1 = s.hist[2 * lane + 1];
        unsigned lsum = v0 + v1;
        unsigned inc = lsum;
        #pragma unroll
        for (int o = 1; o < 32; o <<= 1) {
            unsigned x = __shfl_up_sync(FULL, inc, o);
            if (lane >= o) inc += x;
        }
        unsigned excl = inc - lsum;
        unsigned total = __shfl_sync(FULL, inc, 31);
        bool cross = ((int)excl < TSEL) && ((int)(excl + lsum) >= TSEL);
        unsigned mb = __ballot_sync(FULL, cross);
        if (lane == 0) s.n_valid = (int)total;
        if (mb == 0) {
            if (lane == 0) { s.c1_rel = NHB - 1; s.n_sel = (int)total; }  // take all valid
        } else {
            int src = __ffs(mb) - 1;
            if (lane == src) {
                int rel, incl;
                if ((int)excl + (int)v0 >= TSEL) { rel = 2 * src;     incl = (int)excl + (int)v0; }
                else                             { rel = 2 * src + 1; incl = (int)excl + (int)lsum; }
                if (incl > CAP) s.fb = 1;                      // fat cutoff bin -> fallback
                else            { s.c1_rel = rel; s.n_sel = incl; }
            }
        }
    }
    __syncthreads();

    const int n_sel = s.n_sel;
    const int c1r   = s.c1_rel;

    // ---- compact selected keys (unordered; tail keeps init-time sentinels) ----
    if (!s.fb) {
        for (int m = tid; m < MM; m += 1024) {
            unsigned long long k = s.key[m];
            if ((int)(k >> 52) != 0xFFF && hbin_of(k) <= c1r) {
                int pos = atomicAdd(&s.cnt_sel, 1);
                if (pos < CAP) s.selkey[pos] = k;
            }
        }
    }
    __syncthreads();

    // ---- Phase C: rank sort, 2 threads per element (pairs are warp-aligned) ----
    const int n_pad = (n_sel + 31) & ~31;
    if (tid < 2 * n_pad) {
        int e = tid >> 1, half = tid & 1;
        unsigned long long k = s.selkey[e];
        int j0 = half ? (n_pad >> 1) : 0;
        int j1 = half ? n_pad : (n_pad >> 1);
        int r = 0;
        #pragma unroll 8
        for (int j = j0; j < j1; j++) r += (s.selkey[j] < k);
        r += __shfl_xor_sync(FULL, r, 1);
        if (!half) s.skey[r] = k;
    }
    __syncthreads();

    // ---- Phase D: gather + per-class partition ----
    bool act = false; int lab = 0; float4 bb = make_float4(0.f, 0.f, 0.f, 0.f);
    if (tid < 512) {
        act = (tid < n_sel);
        if (act) {
            int idx = (int)(unsigned)s.skey[tid];
            lab = idx & 1;
            bb = s.box[idx];
            s.sbox[tid] = bb;
        }
        unsigned bal = __ballot_sync(FULL, act && lab);
        if (lane == 0) s.labw[wid] = bal;
    }
    __syncthreads();
    if (tid < 32) {
        unsigned c = (lane < 16) ? __popc(s.labw[lane]) : 0;
        unsigned inc = c;
        #pragma unroll
        for (int o = 1; o < 32; o <<= 1) {
            unsigned x = __shfl_up_sync(FULL, inc, o);
            if (lane >= o) inc += x;
        }
        if (lane < 16) s.pre1[lane] = inc - c;
        unsigned cn1 = __shfl_sync(FULL, inc, 15);
        if (lane == 0) {
            s.cn[1] = (int)cn1;
            s.cn[0] = n_sel - (int)cn1;
            if (s.cn[0] > PCCAP || s.cn[1] > PCCAP) s.fb = 1;
        }
    }
    __syncthreads();
    if (tid < 512 && act) {
        unsigned low = (1u << lane) - 1u;
        int c1below = (int)s.pre1[wid] + __popc(s.labw[wid] & low);
        int r = lab ? c1below : (tid - c1below);
        s.clsrank[tid] = (unsigned short)r;
        if (r < PCCAP) {
            s.cbox[lab][r]  = bb;
            s.carea[lab][r] = (bb.z - bb.x) * (bb.w - bb.y);
        }
    }
    // zero-pad per-class tails (disjoint addresses from scatter above)
    for (int u = tid; u < 2 * PCCAP; u += 1024) {
        int c = u >> 8, r = u & (PCCAP - 1);
        if (r >= min(s.cn[c], PCCAP)) {
            s.cbox[c][r] = make_float4(0.f, 0.f, 0.f, 0.f);
            s.carea[c][r] = 0.f;
        }
    }
    __syncthreads();

    // ---- Phase E: per-class suppression bitmask ----
    for (int u = tid; u < 2 * PCCAP * 8; u += 1024) {
        int c = u >> 11, i = (u >> 3) & (PCCAP - 1), w = u & 7;
        unsigned bits = 0;
        int nc_ = s.cn[c];
        if (i < nc_ && w >= (i >> 5) && (w << 5) < nc_) {
            float4 bi = s.cbox[c][i];
            float  ai = s.carea[c][i];
            int j0 = w << 5;
            #pragma unroll
            for (int l = 0; l < 32; l++) {
                int j = j0 + l;
                float4 bj = s.cbox[c][j];
                float iw = fminf(bi.z, bj.z) - fmaxf(bi.x, bj.x);
                float ih = fminf(bi.w, bj.w) - fmaxf(bi.y, bj.y);
                iw = fmaxf(iw, 0.0f); ih = fmaxf(ih, 0.0f);
                float inter = iw * ih;
                bool sp = (j > i) && (2.0f * inter > ai + s.carea[c][j] - inter + 1e-7f);
                bits |= (sp ? (1u << l) : 0u);
            }
        }
        s.mask[c][i][w] = bits;
    }
    __syncthreads();

    float* oB = out;                              // [B,100,4]
    float* oS = out + BD * MAXDET * 4;            // [B,100]
    float* oL = oS + BD * MAXDET;                 // [B,100]
    float* oK = oL + BD * MAXDET;                 // [B,100]

    // ---- Phase F: per-class greedy resolution (warps 0,1) ∥ output zero-fill (warps 2+) ----
    if (wid < 2) {
        int c = wid;
        int nc_ = min(s.cn[c], PCCAP);
        unsigned removed = 0, kb = 0;
        int cnt = 0;
        for (int i = 0; i < nc_; i++) {
            unsigned rw = __shfl_sync(FULL, removed, i >> 5);
            if (!((rw >> (i & 31)) & 1u)) {
                if (lane == (i >> 5)) kb |= 1u << (i & 31);
                cnt++;
                if (lane < 8) removed |= s.mask[c][i][lane];
                if (cnt == MAXDET) break;
            }
        }
        if (lane < 8) s.kbits[c][lane] = kb;
    } else {
        // zero-fill output while warps 0-1 resolve (ordered before the scatter
        // by the barriers below; fallback overwrites every slot anyway)
        for (int j = tid - 64; j < MAXDET; j += 960) {
            int base = (b * MAXDET + j) * 4;
            oB[base + 0] = 0.f; oB[base + 1] = 0.f; oB[base + 2] = 0.f; oB[base + 3] = 0.f;
            oS[b * MAXDET + j] = 0.f;
            oL[b * MAXDET + j] = 0.f;
            oK[b * MAXDET + j] = 0.f;
        }
    }
    __syncthreads();

    // ---- Phase G: merge kept flags back to global order ----
    bool kflag = false;
    if (tid < 512) {
        if (act) {
            int r = s.clsrank[tid];
            kflag = (s.kbits[lab][r >> 5] >> (r & 31)) & 1u;
        }
        unsigned bal = __ballot_sync(FULL, kflag);
        if (lane == 0) s.kw[wid] = bal;
    }
    __syncthreads();
    if (tid < 32) {
        unsigned c = (lane < 16) ? __popc(s.kw[lane]) : 0;
        unsigned inc = c;
        #pragma unroll
        for (int o = 1; o < 32; o <<= 1) {
            unsigned x = __shfl_up_sync(FULL, inc, o);
            if (lane >= o) inc += x;
        }
        if (lane < 16) s.kpre[lane] = inc - c;
        unsigned tot = __shfl_sync(FULL, inc, 15);
        if (lane == 0) {
            s.kept_total = (int)tot;
            if ((int)tot < MAXDET && s.n_valid > n_sel) s.fb = 1;  // prefix exhausted
        }
    }
    __syncthreads();

    if (!s.fb) {
        // scatter kept rows over the already-zeroed output
        if (tid < 512 && kflag) {
            unsigned low = (1u << lane) - 1u;
            int pos = (int)s.kpre[wid] + __popc(s.kw[wid] & low);
            if (pos < MAXDET) {
                unsigned long long key = s.skey[tid];
                float sc = __uint_as_float((~(unsigned)(key >> 32)) & 0x7FFFFFFFu);
                float4 bx = s.sbox[tid];
                int base = (b * MAXDET + pos) * 4;
                oB[base + 0] = bx.x; oB[base + 1] = bx.y;
                oB[base + 2] = bx.z; oB[base + 3] = bx.w;
                oS[b * MAXDET + pos] = sc;
                oL[b * MAXDET + pos] = (float)(lab + 1);
                oK[b * MAXDET + pos] = 1.0f;
            }
        }
        return;
    }

    // ================= FALLBACK: full bitonic sort + warp NMS =================
    #pragma unroll 1
    for (int k = 2; k <= MM; k <<= 1) {
        #pragma unroll 1
        for (int j = k >> 1; j > 0; j >>= 1) {
            #pragma unroll
            for (int q = 0; q < 2; q++) {
                int p = tid + q * 1024;
                int i = ((p & ~(j - 1)) << 1) | (p & (j - 1));
                int l = i | j;
                bool up = ((i & k) == 0);
                unsigned long long a = s.key[i], c = s.key[l];
                if ((a > c) == up) { s.key[i] = c; s.key[l] = a; }
            }
            __syncthreads();
        }
    }
    for (int t = tid; t < PRE; t += 1024) {
        int idx = (int)(unsigned)s.key[t];
        s.sbox[t] = s.box[idx];
    }
    __syncthreads();

    if (tid < 32) {
        int cnt = 0;
        for (int t = 0; t < MM; t++) {
            unsigned long long key = s.key[t];
            unsigned hi = (unsigned)(key >> 32);
            if (hi == 0xFFFFFFFFu) break;
            int idx = (int)(unsigned)key;
            int lb = idx & 1;
            float sc = __uint_as_float((~hi) & 0x7FFFFFFFu);
            float4 bc = (t < PRE) ? s.sbox[t] : s.box[idx];
            float area = (bc.z - bc.x) * (bc.w - bc.y);
            bool sup = false;
            for (int j = lane; j < cnt; j += 32) {
                if (s.klab[j] == lb) {
                    float4 kb = s.kbox[j];
                    float iw = fminf(bc.z, kb.z) - fmaxf(bc.x, kb.x);
                    float ih = fminf(bc.w, kb.w) - fmaxf(bc.y, kb.y);
                    iw = fmaxf(iw, 0.0f); ih = fmaxf(ih, 0.0f);
                    float inter = iw * ih;
                    if (2.0f * inter > area + s.karea[j] - inter + 1e-7f) sup = true;
                }
            }
            if (__ballot_sync(FULL, sup) == 0u) {
                if (lane == 0) {
                    s.kbox[cnt] = bc; s.karea[cnt] = area;
                    s.kscore[cnt] = sc; s.klab[cnt] = lb;
                }
                cnt++;
                __syncwarp();
                if (cnt == MAXDET) break;
            }
        }
        if (lane == 0) s.s_cnt = cnt;
    }
    __syncthreads();

    int cnt = s.s_cnt;
    for (int j = tid; j < MAXDET; j += 1024) {
        bool k = (j < cnt);
        float4 bc = k ? s.kbox[j] : make_float4(0.f, 0.f, 0.f, 0.f);
        int base = (b * MAXDET + j) * 4;
        oB[base + 0] = bc.x; oB[base + 1] = bc.y;
        oB[base + 2] = bc.z; oB[base + 3] = bc.w;
        oS[b * MAXDET + j] = k ? s.kscore[j] : 0.0f;
        oL[b * MAXDET + j] = k ? (float)(s.klab[j] + 1) : 0.0f;
        oK[b * MAXDET + j] = k ? 1.0f : 0.0f;
    }
}

// ---------------------------------------------------------------------------
extern "C" void kernel_launch(void* const* d_in, const int* in_sizes, int n_in,
                              void* d_out, int out_size) {
    const float* logits = nullptr;
    const float* reg    = nullptr;
    const float* props  = nullptr;
    const void*  dims[2] = {nullptr, nullptr};
    int nd = 0;
    for (int i = 0; i < n_in; i++) {
        int sz = in_sizes[i];
        if      (sz == BD * NP * 3)  logits = (const float*)d_in[i];
        else if (sz == BD * NP * 12) reg    = (const float*)d_in[i];
        else if (sz == BD * NP * 4)  props  = (const float*)d_in[i];
        else if (sz == 1 && nd < 2)  dims[nd++] = d_in[i];
    }

    const int smem_bytes = (int)sizeof(SM);
    cudaFuncSetAttribute(fused_kernel, cudaFuncAttributeMaxDynamicSharedMemorySize, smem_bytes);
    fused_kernel<<<BD, 1024, smem_bytes>>>(logits, reg, props, dims[0], dims[1], (float*)d_out);
}